// round 10
// baseline (speedup 1.0000x reference)
#include <cuda_runtime.h>
#include <math.h>

#define BB 2
#define NN 8192
#define KNN 16
#define CIN 32
#define FULLW 0xffffffffu

// spatial grid
#define GD 32
#define NCELL (GD*GD*GD)
#define GH 0.4f
#define GMIN (-6.4f)

// ---------------- scratch ----------------
__device__ float  g_feat_t[BB*NN*CIN];
__device__ int    g_cnt[BB*NCELL];
__device__ int    g_cstart[BB*NCELL];
__device__ int    g_cursor[BB*NCELL];
__device__ float4 g_pts[BB*NN];    // (x, y, z, pid-as-float) sorted by cell
__device__ float4 g_nb[BB*NN*KNN]; // (nx, ny, nz, dist) per point per k
// weights, repacked by prep
__device__ float g_mlp1Wt[32*32];
__device__ float g_lse1We[3*32];
__device__ float g_lse1Wn[4*32];
__device__ float g_lse2We[3*32];
__device__ float g_lse2Wn[4*32];
__device__ float g_p1c1p[512];
__device__ float g_p1c2p[512];
__device__ float g_p1wmt[64*32];
__device__ float g_p2c1p[512];
__device__ float g_p2c2p[512];
__device__ float g_p2wmt[64*64];
__device__ float g_mlp2t[64*128];
__device__ float g_scWt[32*128];   // pre-scaled by sc_g*bns

// ---------------- prep: weights + grid_zero + feat transpose, one kernel ----------------
__global__ void prep_all(
    const float* __restrict__ mlp1_W,
    const float* __restrict__ lse1_W,
    const float* __restrict__ lse2_W,
    const float* __restrict__ p1c1, const float* __restrict__ p1c2, const float* __restrict__ p1wm,
    const float* __restrict__ p2c1, const float* __restrict__ p2c2, const float* __restrict__ p2wm,
    const float* __restrict__ mlp2_W, const float* __restrict__ sc_W,
    const float* __restrict__ sc_g, const float* __restrict__ features)
{
    const float bns = rsqrtf(1.0f + 1e-5f);
    int t = threadIdx.x;
    int bid = blockIdx.x;
    if (bid < 11) {
        switch (bid) {
            case 0:
                for (int i = t; i < 32*32; i += 256) g_mlp1Wt[(i%32)*32 + (i/32)] = mlp1_W[i];
                break;
            case 1:
                if (t < 32) {
                    for (int d = 0; d < 3; d++) {
                        g_lse1We[d*32+t] = lse1_W[t*10+d]   + lse1_W[t*10+6+d];
                        g_lse1Wn[d*32+t] = lse1_W[t*10+3+d] - lse1_W[t*10+6+d];
                    }
                    g_lse1Wn[3*32+t] = lse1_W[t*10+9];
                }
                break;
            case 2:
                if (t < 32) {
                    for (int d = 0; d < 3; d++) {
                        g_lse2We[d*32+t] = lse2_W[t*10+d]   + lse2_W[t*10+6+d];
                        g_lse2Wn[d*32+t] = lse2_W[t*10+3+d] - lse2_W[t*10+6+d];
                    }
                    g_lse2Wn[3*32+t] = lse2_W[t*10+9];
                }
                break;
            case 3:
                for (int i = t; i < 512; i += 256) {
                    int j = i / 64, c = i % 64;
                    g_p1c1p[((c>>2)*8 + j)*4 + (c&3)] = p1c1[i];
                }
                break;
            case 4:
                for (int i = t; i < 512; i += 256) {
                    int r = i / 8, c = i % 8;
                    g_p1c2p[((c>>2)*64 + r)*4 + (c&3)] = p1c2[i];
                }
                break;
            case 5:
                for (int i = t; i < 32*64; i += 256) g_p1wmt[(i%64)*32 + (i/64)] = p1wm[i];
                break;
            case 6:
                for (int i = t; i < 512; i += 256) {
                    int j = i / 64, c = i % 64;
                    g_p2c1p[((c>>2)*8 + j)*4 + (c&3)] = p2c1[i];
                }
                break;
            case 7:
                for (int i = t; i < 512; i += 256) {
                    int r = i / 8, c = i % 8;
                    g_p2c2p[((c>>2)*64 + r)*4 + (c&3)] = p2c2[i];
                }
                break;
            case 8:
                for (int i = t; i < 64*64; i += 256) g_p2wmt[(i%64)*64 + (i/64)] = p2wm[i];
                break;
            case 9:
                for (int i = t; i < 128*64; i += 256) g_mlp2t[(i%64)*128 + (i/64)] = mlp2_W[i];
                break;
            default:
                for (int i = t; i < 128*32; i += 256) {
                    int oc = i / 32, d = i % 32;
                    g_scWt[d*128 + oc] = sc_W[i] * sc_g[oc] * bns;
                }
                break;
        }
        return;
    }
    bid -= 11;
    if (bid < (BB*NCELL)/256) {          // grid_zero
        g_cnt[bid*256 + t] = 0;
        return;
    }
    bid -= (BB*NCELL)/256;
    {                                     // feat transpose
        int gid = bid*256 + t;
        if (gid < BB*NN*CIN) {
            int c = gid & 31;
            int p = gid >> 5;
            int b = p / NN, n = p % NN;
            g_feat_t[gid] = features[((size_t)b*CIN + c)*NN + n];
        }
    }
}

// ---------------- grid binning ----------------
__device__ __forceinline__ int cell_coord(float x) {
    int c = (int)floorf((x - GMIN) * (1.0f/GH));
    return min(GD-1, max(0, c));
}

__global__ void grid_count(const float* __restrict__ coords) {
    int p = blockIdx.x * blockDim.x + threadIdx.x;
    if (p >= BB*NN) return;
    int b = p / NN;
    float x = coords[p*3+0], y = coords[p*3+1], z = coords[p*3+2];
    int cid = (cell_coord(x)*GD + cell_coord(y))*GD + cell_coord(z);
    atomicAdd(&g_cnt[b*NCELL + cid], 1);
}

// one block per batch; 1024 threads, 32 cells each
__global__ void grid_scan() {
    __shared__ int ss[1024];
    int b = blockIdx.x;
    int t = threadIdx.x;
    int base = b*NCELL + t*32;
    int loc[32];
    int sum = 0;
#pragma unroll
    for (int i = 0; i < 32; i++) { loc[i] = g_cnt[base + i]; sum += loc[i]; }
    ss[t] = sum;
    __syncthreads();
    for (int off = 1; off < 1024; off <<= 1) {
        int v = (t >= off) ? ss[t-off] : 0;
        __syncthreads();
        ss[t] += v;
        __syncthreads();
    }
    int run = (t > 0) ? ss[t-1] : 0;
#pragma unroll
    for (int i = 0; i < 32; i++) {
        g_cstart[base + i] = run;
        g_cursor[base + i] = run;
        run += loc[i];
    }
}

__global__ void grid_scatter(const float* __restrict__ coords) {
    int p = blockIdx.x * blockDim.x + threadIdx.x;
    if (p >= BB*NN) return;
    int b = p / NN, n = p % NN;
    float x = coords[p*3+0], y = coords[p*3+1], z = coords[p*3+2];
    int cid = (cell_coord(x)*GD + cell_coord(y))*GD + cell_coord(z);
    int pos = atomicAdd(&g_cursor[b*NCELL + cid], 1);
    g_pts[b*NN + pos] = make_float4(x, y, z, __int_as_float(n));
}

// ---------------- KNN v5: 1 query/warp, buffered candidates + bitonic sort-merge ----------------
__device__ __forceinline__ void bitonic32(float& key, int& pay, int lane) {
#pragma unroll
    for (int k = 2; k <= 32; k <<= 1) {
#pragma unroll
        for (int j = k >> 1; j > 0; j >>= 1) {
            float ok = __shfl_xor_sync(FULLW, key, j);
            int   op = __shfl_xor_sync(FULLW, pay, j);
            bool takeMin = (((lane & j) == 0) == ((lane & k) == 0));
            bool less = (ok < key) || (ok == key && op < pay);
            if (takeMin ? less : !less) { key = ok; pay = op; }
        }
    }
}

// merge sorted top-16 (lanes 0..15 of lv/li, ascending) with a sorted-asc 32-chunk
__device__ __forceinline__ void merge_chunk(
    float key, int pay, float& lv, int& li, float& tau, int lane)
{
    float ck = __shfl_xor_sync(FULLW, key, 31);   // lanes 16..31 <- chunk[15..0] (desc)
    int   cp = __shfl_xor_sync(FULLW, pay, 31);
    float v  = (lane < 16) ? lv : ck;
    int   vp = (lane < 16) ? li : cp;
#pragma unroll
    for (int j = 16; j > 0; j >>= 1) {
        float ov  = __shfl_xor_sync(FULLW, v, j);
        int   ovp = __shfl_xor_sync(FULLW, vp, j);
        bool takeMin = ((lane & j) == 0);
        bool less = (ov < v) || (ov == v && ovp < vp);
        if (takeMin ? less : !less) { v = ov; vp = ovp; }
    }
    lv = v; li = vp;
    tau = __shfl_sync(FULLW, v, 15);
}

__device__ __forceinline__ void flush_full(
    volatile float* bD, volatile int* bA, int base,
    float& lv, int& li, float& tau, int lane)
{
    __syncwarp();
    float key = bD[base + lane];
    int   pay = bA[base + lane];
    bitonic32(key, pay, lane);
    merge_chunk(key, pay, lv, li, tau, lane);
}

__device__ __forceinline__ void flush_partial(
    volatile float* bD, volatile int* bA, int& nbuf,
    float& lv, int& li, float& tau, int lane)
{
    if (nbuf > 0) {
        __syncwarp();
        float key = (lane < nbuf) ? bD[lane] : 3.4e38f;
        int   pay = (lane < nbuf) ? bA[lane] : 0x7fffffff;
        bitonic32(key, pay, lane);
        merge_chunk(key, pay, lv, li, tau, lane);
        nbuf = 0;
    }
}

__device__ __forceinline__ void stream_run(
    int s0, int e0, const float4* __restrict__ pts,
    float qx, float qy, float qz,
    float& lv, int& li, float& tau, bool& seeded, int& nbuf,
    volatile float* bD, volatile int* bA, int lane)
{
    for (int f = s0; f < e0; f += 32) {
        int a = f + lane;
        float d2 = 3.4e38f;
        if (a < e0) {
            float4 c = pts[a];
            float dx = qx - c.x, dy = qy - c.y, dz = qz - c.z;
            d2 = fmaf(dx, dx, fmaf(dy, dy, dz*dz));
        }
        if (!seeded) {
            float key = d2;
            int pay = (a < e0) ? a : 0x7fffffff;
            bitonic32(key, pay, lane);
            lv = (lane < 16) ? key : 3.4e38f;
            li = pay;
            tau = __shfl_sync(FULLW, key, 15);
            seeded = true;
            continue;
        }
        unsigned m = __ballot_sync(FULLW, d2 < tau);
        if (m) {
            int rank = __popc(m & ((1u << lane) - 1u));
            if (d2 < tau) { bD[nbuf + rank] = d2; bA[nbuf + rank] = a; }
            nbuf += __popc(m);
            while (nbuf >= 32) {
                nbuf -= 32;
                flush_full(bD, bA, nbuf, lv, li, tau, lane);
            }
        }
    }
}

__global__ void __launch_bounds__(256) knn_grid() {
    __shared__ float sD[8][64];
    __shared__ int   sA[8][64];
    int b = blockIdx.y;
    int warp = threadIdx.x >> 5, lane = threadIdx.x & 31;
    int sp = blockIdx.x * 8 + warp;              // sorted position
    const float4* pts = g_pts + (size_t)b*NN;
    const int*    ccnt = g_cnt + (size_t)b*NCELL;
    const int*    cst  = g_cstart + (size_t)b*NCELL;
    volatile float* bD = sD[warp];
    volatile int*   bA = sA[warp];

    float4 qp = pts[sp];
    float qx = qp.x, qy = qp.y, qz = qp.z;
    int qpid = __float_as_int(qp.w);
    int cx = cell_coord(qx), cy = cell_coord(qy), cz = cell_coord(qz);

    float lv = 3.4e38f; int li = 0x7fffffff;
    float tau = 3.4e38f;
    bool seeded = false;
    int nbuf = 0;

    int lx = cx-1, hx = cx+1, ly = cy-1, hy = cy+1, lz = cz-1, hz = cz+1;

    // ---- initial 3x3 columns, center-out (lanes 0-8 fetch bounds in parallel) ----
    {
        int st = 0, en = 0;
        if (lane < 9) {
            int dx = ((0x28161 >> (2*lane)) & 3) - 1;
            int dy = ((0x22215 >> (2*lane)) & 3) - 1;
            int X = cx + dx, Y = cy + dy;
            if (X >= 0 && X < GD && Y >= 0 && Y < GD) {
                int zl = max(lz, 0), zh = min(hz, GD-1);
                int base = (X*GD + Y)*GD;
                st = cst[base + zl];
                en = cst[base + zh] + ccnt[base + zh];
            }
        }
#pragma unroll
        for (int rr = 0; rr < 9; rr++) {
            int s0 = __shfl_sync(FULLW, st, rr);
            int e0 = __shfl_sync(FULLW, en, rr);
            if (s0 < e0) stream_run(s0, e0, pts, qx, qy, qz,
                                    lv, li, tau, seeded, nbuf, bD, bA, lane);
        }
    }

    // ---- shells: expand box by 1 until provably done ----
    while (true) {
        flush_partial(bD, bA, nbuf, lv, li, tau, lane);
        bool covered = (lx <= 0) && (ly <= 0) && (lz <= 0) &&
                       (hx >= GD-1) && (hy >= GD-1) && (hz >= GD-1);
        if (covered) break;
        float dmin = 3.4e38f;
        if (lx > 0)    dmin = fminf(dmin, qx - (GMIN + lx*GH));
        if (hx < GD-1) dmin = fminf(dmin, (GMIN + (hx+1)*GH) - qx);
        if (ly > 0)    dmin = fminf(dmin, qy - (GMIN + ly*GH));
        if (hy < GD-1) dmin = fminf(dmin, (GMIN + (hy+1)*GH) - qy);
        if (lz > 0)    dmin = fminf(dmin, qz - (GMIN + lz*GH));
        if (hz < GD-1) dmin = fminf(dmin, (GMIN + (hz+1)*GH) - qz);
        if (tau < dmin*dmin - 1e-4f) break;

        lx--; hx++; ly--; hy++; lz--; hz++;
        int W = hx - lx + 1, H = hy - ly + 1;
        int ncols = W * H;
        for (int cb = 0; cb < ncols; cb += 32) {
            int c = cb + lane;
            int st1 = 0, en1 = 0, st2 = 0, en2 = 0;
            if (c < ncols) {
                int X = lx + c / H, Y = ly + c % H;
                if (X >= 0 && X < GD && Y >= 0 && Y < GD) {
                    bool per = (X == lx) || (X == hx) || (Y == ly) || (Y == hy);
                    int base = (X*GD + Y)*GD;
                    if (per) {
                        int zl = max(lz, 0), zh = min(hz, GD-1);
                        if (zl <= zh) { st1 = cst[base + zl]; en1 = cst[base + zh] + ccnt[base + zh]; }
                    } else {
                        if (lz >= 0 && lz < GD) { st1 = cst[base + lz]; en1 = st1 + ccnt[base + lz]; }
                        if (hz >= 0 && hz < GD) { st2 = cst[base + hz]; en2 = st2 + ccnt[base + hz]; }
                    }
                }
            }
            int lim = min(32, ncols - cb);
            for (int rr = 0; rr < lim; rr++) {
                int s0 = __shfl_sync(FULLW, st1, rr);
                int e0 = __shfl_sync(FULLW, en1, rr);
                if (s0 < e0) stream_run(s0, e0, pts, qx, qy, qz,
                                        lv, li, tau, seeded, nbuf, bD, bA, lane);
                int s1 = __shfl_sync(FULLW, st2, rr);
                int e1 = __shfl_sync(FULLW, en2, rr);
                if (s1 < e1) stream_run(s1, e1, pts, qx, qy, qz,
                                        lv, li, tau, seeded, nbuf, bD, bA, lane);
            }
        }
    }

    if (lane < KNN) {
        float4 c = pts[li];
        g_nb[((size_t)b*NN + qpid)*KNN + lane] = make_float4(c.x, c.y, c.z, sqrtf(lv));
    }
}

// ---------------- fused per-point pipeline (8 points per 256-thread block) ----------------
__device__ __forceinline__ float sigmoidf_(float x) { return 1.0f / (1.0f + expf(-x)); }

struct SArena {
    float4 nb[8][16];
    float  A[8][64];
    float  M[8][64];
    float  Hs[8][8];
    float  Sp[8][16];
    float  Fe8[32*8];
    float  F8[64*8];
    float  Out8[64*8];
    float  Part[4096];
};

template<int NOUT>
__device__ __forceinline__ void stage(
    SArena* s, float featv, float cx, float cy, float cz,
    const float* __restrict__ We, const float* __restrict__ Wn,
    const float* __restrict__ bl, const float* __restrict__ gl, const float* __restrict__ btl,
    const float* __restrict__ c1p, const float* __restrict__ c2p,
    const float* __restrict__ Ws,
    const float* __restrict__ Wmt, const float* __restrict__ bm,
    const float* __restrict__ gm,  const float* __restrict__ btm,
    int lane, int warp, int tid)
{
    const float bns = rsqrtf(1.0f + 1e-5f);
    float we0 = We[0*32+lane], we1 = We[1*32+lane], we2 = We[2*32+lane];
    float wn0 = Wn[0*32+lane], wn1 = Wn[1*32+lane], wn2 = Wn[2*32+lane], wn3 = Wn[3*32+lane];
    float scl = gl[lane]*bns, shb = btl[lane];
    float base = bl[lane];
    base = fmaf(we0, cx, fmaf(we1, cy, fmaf(we2, cz, base)));

    float e[16];
    float avg = 0.f, mx = -3.4e38f;
#pragma unroll
    for (int k = 0; k < 16; k++) {
        float4 nb = s->nb[warp][k];
        float v = fmaf(wn0, nb.x, fmaf(wn1, nb.y, fmaf(wn2, nb.z, fmaf(wn3, nb.w, base))));
        v = fmaxf(scl*v + shb, 0.f);
        e[k] = v;
        avg += v;
        mx = fmaxf(mx, v);
    }
    avg *= 0.0625f;
    s->A[warp][lane] = avg; s->A[warp][32 + lane] = featv;
    s->M[warp][lane] = mx;  s->M[warp][32 + lane] = featv;
    __syncwarp();

    {
        int j = lane & 7;
        int srcbit = (lane >> 3) & 1;
        int chalf = lane >> 4;
        const float* S = srcbit ? s->M[warp] : s->A[warp];
        float h = 0.f;
#pragma unroll
        for (int cq = 0; cq < 8; cq++) {
            int quad = chalf*8 + cq;
            float4 w4 = *reinterpret_cast<const float4*>(&c1p[(quad*8 + j)*4]);
            float4 a4 = *reinterpret_cast<const float4*>(&S[chalf*32 + cq*4]);
            h = fmaf(w4.x, a4.x, fmaf(w4.y, a4.y, fmaf(w4.z, a4.z, fmaf(w4.w, a4.w, h))));
        }
        h += __shfl_xor_sync(FULLW, h, 16);
        float h2 = fmaxf(h, 0.f);
        float hsv = h2 + __shfl_xor_sync(FULLW, h2, 8);
        if (lane < 8) s->Hs[warp][lane] = hsv;
    }
    __syncwarp();

    float4 hs0 = *reinterpret_cast<const float4*>(&s->Hs[warp][0]);
    float4 hs1 = *reinterpret_cast<const float4*>(&s->Hs[warp][4]);
    float a, b2;
    {
        float4 w0 = *reinterpret_cast<const float4*>(&c2p[lane*4]);
        float4 w1 = *reinterpret_cast<const float4*>(&c2p[(64 + lane)*4]);
        a = w0.x*hs0.x + w0.y*hs0.y + w0.z*hs0.z + w0.w*hs0.w
          + w1.x*hs1.x + w1.y*hs1.y + w1.z*hs1.z + w1.w*hs1.w;
        float4 v0 = *reinterpret_cast<const float4*>(&c2p[(32 + lane)*4]);
        float4 v1 = *reinterpret_cast<const float4*>(&c2p[(96 + lane)*4]);
        b2 = v0.x*hs0.x + v0.y*hs0.y + v0.z*hs0.z + v0.w*hs0.w
           + v1.x*hs1.x + v1.y*hs1.y + v1.z*hs1.z + v1.w*hs1.w;
    }
    float chA = sigmoidf_(a), chB = sigmoidf_(b2);
    float xf = featv * chB;

    float vs[16], vm[16];
#pragma unroll
    for (int k = 0; k < 16; k++) {
        float ek = e[k] * chA;
        e[k] = ek;
        vs[k] = ek + xf;
        vm[k] = fmaxf(ek, xf);
    }
    {
        bool up = (lane & 16);
#pragma unroll
        for (int i = 0; i < 8; i++) {
            float ss = up ? vs[i] : vs[i+8];
            float ks = up ? vs[i+8] : vs[i];
            vs[i] = ks + __shfl_xor_sync(FULLW, ss, 16);
            float sm2 = up ? vm[i] : vm[i+8];
            float km = up ? vm[i+8] : vm[i];
            vm[i] = fmaxf(km, __shfl_xor_sync(FULLW, sm2, 16));
        }
    }
    {
        bool up = (lane & 8);
#pragma unroll
        for (int i = 0; i < 4; i++) {
            float ss = up ? vs[i] : vs[i+4];
            float ks = up ? vs[i+4] : vs[i];
            vs[i] = ks + __shfl_xor_sync(FULLW, ss, 8);
            float sm2 = up ? vm[i] : vm[i+4];
            float km = up ? vm[i+4] : vm[i];
            vm[i] = fmaxf(km, __shfl_xor_sync(FULLW, sm2, 8));
        }
    }
    {
        bool up = (lane & 4);
#pragma unroll
        for (int i = 0; i < 2; i++) {
            float ss = up ? vs[i] : vs[i+2];
            float ks = up ? vs[i+2] : vs[i];
            vs[i] = ks + __shfl_xor_sync(FULLW, ss, 4);
            float sm2 = up ? vm[i] : vm[i+2];
            float km = up ? vm[i+2] : vm[i];
            vm[i] = fmaxf(km, __shfl_xor_sync(FULLW, sm2, 4));
        }
    }
    {
        bool up = (lane & 2);
        float ss = up ? vs[0] : vs[1];
        float ks = up ? vs[1] : vs[0];
        vs[0] = ks + __shfl_xor_sync(FULLW, ss, 2);
        float sm2 = up ? vm[0] : vm[1];
        float km = up ? vm[1] : vm[0];
        vm[0] = fmaxf(km, __shfl_xor_sync(FULLW, sm2, 2));
    }
    vs[0] += __shfl_xor_sync(FULLW, vs[0], 1);
    vm[0] = fmaxf(vm[0], __shfl_xor_sync(FULLW, vm[0], 1));

    float ws0 = Ws[0], ws1 = Ws[1];
    float sp = sigmoidf_(ws0 * vs[0] * (1.0f/64.0f) + ws1 * vm[0]);
    int kL = (((lane>>4)&1)<<3) | (((lane>>3)&1)<<2) | (((lane>>2)&1)<<1) | ((lane>>1)&1);
    if (!(lane & 1)) s->Sp[warp][kL] = sp;
    float sps = sp;
#pragma unroll
    for (int off = 16; off > 0; off >>= 1) sps += __shfl_xor_sync(FULLW, sps, off);
    sps *= 0.5f;
    __syncwarp();

    float fA = 0.f;
#pragma unroll
    for (int k = 0; k < 16; k++) fA = fmaf(e[k], s->Sp[warp][k], fA);

    s->F8[lane*8 + warp]        = fA;
    s->F8[(32 + lane)*8 + warp] = xf * sps;
    __syncthreads();

    constexpr int G = NOUT/32;
    {
        float acc[G][8];
#pragma unroll
        for (int g = 0; g < G; g++)
#pragma unroll
            for (int p = 0; p < 8; p++) acc[g][p] = 0.f;
        int jb = warp * 8;
#pragma unroll
        for (int jj = 0; jj < 8; jj++) {
            int j = jb + jj;
            float4 a0 = *reinterpret_cast<const float4*>(&s->F8[j*8]);
            float4 a1 = *reinterpret_cast<const float4*>(&s->F8[j*8+4]);
#pragma unroll
            for (int g = 0; g < G; g++) {
                float wv = Wmt[j*NOUT + g*32 + lane];
                acc[g][0] = fmaf(wv, a0.x, acc[g][0]);
                acc[g][1] = fmaf(wv, a0.y, acc[g][1]);
                acc[g][2] = fmaf(wv, a0.z, acc[g][2]);
                acc[g][3] = fmaf(wv, a0.w, acc[g][3]);
                acc[g][4] = fmaf(wv, a1.x, acc[g][4]);
                acc[g][5] = fmaf(wv, a1.y, acc[g][5]);
                acc[g][6] = fmaf(wv, a1.z, acc[g][6]);
                acc[g][7] = fmaf(wv, a1.w, acc[g][7]);
            }
        }
#pragma unroll
        for (int g = 0; g < G; g++) {
            int bidx = (warp*NOUT + g*32 + lane)*8;
            *reinterpret_cast<float4*>(&s->Part[bidx])   = make_float4(acc[g][0], acc[g][1], acc[g][2], acc[g][3]);
            *reinterpret_cast<float4*>(&s->Part[bidx+4]) = make_float4(acc[g][4], acc[g][5], acc[g][6], acc[g][7]);
        }
    }
    __syncthreads();

#pragma unroll
    for (int g = 0; g < G; g++) {
        int idx = g*256 + tid;
        int oc = idx >> 3, pp = idx & 7;
        float sum = 0.f;
#pragma unroll
        for (int w = 0; w < 8; w++) sum += s->Part[(w*NOUT + oc)*8 + pp];
        sum += bm[oc];
        s->Out8[idx] = fmaxf(gm[oc]*bns*sum + btm[oc], 0.f);
    }
    __syncthreads();
}

__global__ void __launch_bounds__(256) fused_kernel(
    const float* __restrict__ coords,
    const float* __restrict__ mlp1_b,
    const float* __restrict__ lse1_b, const float* __restrict__ lse1_g, const float* __restrict__ lse1_bt,
    const float* __restrict__ p1_Ws,  const float* __restrict__ p1_bm,  const float* __restrict__ p1_g, const float* __restrict__ p1_bt,
    const float* __restrict__ lse2_b, const float* __restrict__ lse2_g, const float* __restrict__ lse2_bt,
    const float* __restrict__ p2_Ws,  const float* __restrict__ p2_bm,  const float* __restrict__ p2_g, const float* __restrict__ p2_bt,
    const float* __restrict__ mlp2_b,
    const float* __restrict__ sc_b, const float* __restrict__ sc_g, const float* __restrict__ sc_bt,
    float* __restrict__ out)
{
    __shared__ SArena s;

    int tid = threadIdx.x;
    int warp = tid >> 5, lane = tid & 31;
    int p = blockIdx.x * 8 + warp;
    int b = p >> 13, n = p & (NN - 1);

    s.Fe8[lane*8 + warp] = g_feat_t[p*CIN + lane];

    const float* cb = coords + ((size_t)b*NN + n)*3;
    float cx = cb[0], cy = cb[1], cz = cb[2];
    if (lane < 16) {
        s.nb[warp][lane] = g_nb[(size_t)p*KNN + lane];
    }
    __syncwarp();

    float x1;
    {
        float acc = mlp1_b[lane];
#pragma unroll
        for (int d = 0; d < 32; d++) acc = fmaf(g_mlp1Wt[d*32 + lane], s.Fe8[d*8 + warp], acc);
        x1 = acc >= 0.f ? acc : 0.2f*acc;
    }

    stage<32>(&s, x1, cx, cy, cz, g_lse1We, g_lse1Wn, lse1_b, lse1_g, lse1_bt,
              g_p1c1p, g_p1c2p, p1_Ws, g_p1wmt, p1_bm, p1_g, p1_bt, lane, warp, tid);
    float o1 = s.Out8[lane*8 + warp];

    stage<64>(&s, o1, cx, cy, cz, g_lse2We, g_lse2Wn, lse2_b, lse2_g, lse2_bt,
              g_p2c1p, g_p2c2p, p2_Ws, g_p2wmt, p2_bm, p2_g, p2_bt, lane, warp, tid);

    {
        int slice = tid >> 6;
        int oc0 = (tid & 63) * 2;
        float acc0[8], acc1[8];
#pragma unroll
        for (int q = 0; q < 8; q++) { acc0[q] = 0.f; acc1[q] = 0.f; }
#pragma unroll
        for (int jj = 0; jj < 16; jj++) {
            int j = slice*16 + jj;
            float2 w2 = *reinterpret_cast<const float2*>(&g_mlp2t[j*128 + oc0]);
            float4 a0 = *reinterpret_cast<const float4*>(&s.Out8[j*8]);
            float4 a1 = *reinterpret_cast<const float4*>(&s.Out8[j*8+4]);
            acc0[0] = fmaf(w2.x, a0.x, acc0[0]); acc1[0] = fmaf(w2.y, a0.x, acc1[0]);
            acc0[1] = fmaf(w2.x, a0.y, acc0[1]); acc1[1] = fmaf(w2.y, a0.y, acc1[1]);
            acc0[2] = fmaf(w2.x, a0.z, acc0[2]); acc1[2] = fmaf(w2.y, a0.z, acc1[2]);
            acc0[3] = fmaf(w2.x, a0.w, acc0[3]); acc1[3] = fmaf(w2.y, a0.w, acc1[3]);
            acc0[4] = fmaf(w2.x, a1.x, acc0[4]); acc1[4] = fmaf(w2.y, a1.x, acc1[4]);
            acc0[5] = fmaf(w2.x, a1.y, acc0[5]); acc1[5] = fmaf(w2.y, a1.y, acc1[5]);
            acc0[6] = fmaf(w2.x, a1.z, acc0[6]); acc1[6] = fmaf(w2.y, a1.z, acc1[6]);
            acc0[7] = fmaf(w2.x, a1.w, acc0[7]); acc1[7] = fmaf(w2.y, a1.w, acc1[7]);
        }
#pragma unroll
        for (int dd = 0; dd < 8; dd++) {
            int d = slice*8 + dd;
            float2 w2 = *reinterpret_cast<const float2*>(&g_scWt[d*128 + oc0]);
            float4 f0 = *reinterpret_cast<const float4*>(&s.Fe8[d*8]);
            float4 f1 = *reinterpret_cast<const float4*>(&s.Fe8[d*8+4]);
            acc0[0] = fmaf(w2.x, f0.x, acc0[0]); acc1[0] = fmaf(w2.y, f0.x, acc1[0]);
            acc0[1] = fmaf(w2.x, f0.y, acc0[1]); acc1[1] = fmaf(w2.y, f0.y, acc1[1]);
            acc0[2] = fmaf(w2.x, f0.z, acc0[2]); acc1[2] = fmaf(w2.y, f0.z, acc1[2]);
            acc0[3] = fmaf(w2.x, f0.w, acc0[3]); acc1[3] = fmaf(w2.y, f0.w, acc1[3]);
            acc0[4] = fmaf(w2.x, f1.x, acc0[4]); acc1[4] = fmaf(w2.y, f1.x, acc1[4]);
            acc0[5] = fmaf(w2.x, f1.y, acc0[5]); acc1[5] = fmaf(w2.y, f1.y, acc1[5]);
            acc0[6] = fmaf(w2.x, f1.z, acc0[6]); acc1[6] = fmaf(w2.y, f1.z, acc1[6]);
            acc0[7] = fmaf(w2.x, f1.w, acc0[7]); acc1[7] = fmaf(w2.y, f1.w, acc1[7]);
        }
        int b0 = (slice*128 + oc0)*8;
        *reinterpret_cast<float4*>(&s.Part[b0])     = make_float4(acc0[0], acc0[1], acc0[2], acc0[3]);
        *reinterpret_cast<float4*>(&s.Part[b0+4])   = make_float4(acc0[4], acc0[5], acc0[6], acc0[7]);
        *reinterpret_cast<float4*>(&s.Part[b0+8])   = make_float4(acc1[0], acc1[1], acc1[2], acc1[3]);
        *reinterpret_cast<float4*>(&s.Part[b0+12])  = make_float4(acc1[4], acc1[5], acc1[6], acc1[7]);
    }
    __syncthreads();

    {
        const float bns = rsqrtf(1.0f + 1e-5f);
        int oc = tid & 127;
        int ph = tid >> 7;
        float4 v = make_float4(0.f, 0.f, 0.f, 0.f);
#pragma unroll
        for (int sl = 0; sl < 4; sl++) {
            float4 t = *reinterpret_cast<const float4*>(&s.Part[(sl*128 + oc)*8 + ph*4]);
            v.x += t.x; v.y += t.y; v.z += t.z; v.w += t.w;
        }
        float basev = mlp2_b[oc] + sc_g[oc]*bns*sc_b[oc] + sc_bt[oc];
        v.x += basev; v.y += basev; v.z += basev; v.w += basev;
        v.x = v.x >= 0.f ? v.x : 0.01f*v.x;
        v.y = v.y >= 0.f ? v.y : 0.01f*v.y;
        v.z = v.z >= 0.f ? v.z : 0.01f*v.z;
        v.w = v.w >= 0.f ? v.w : 0.01f*v.w;

        int p0 = blockIdx.x * 8;
        int b0 = p0 >> 13, n0 = p0 & (NN - 1);
        *reinterpret_cast<float4*>(&out[((size_t)(b0*128 + oc))*NN + n0 + ph*4]) = v;
    }
}

// ---------------- launch ----------------
extern "C" void kernel_launch(void* const* d_in, const int* in_sizes, int n_in,
                              void* d_out, int out_size) {
    const float* coords   = (const float*)d_in[0];
    const float* features = (const float*)d_in[1];
    const float* mlp1_W = (const float*)d_in[2];
    const float* mlp1_b = (const float*)d_in[3];
    const float* lse1_W = (const float*)d_in[4];
    const float* lse1_b = (const float*)d_in[5];
    const float* lse1_g = (const float*)d_in[6];
    const float* lse1_bt = (const float*)d_in[7];
    const float* p1_Wc1 = (const float*)d_in[8];
    const float* p1_Wc2 = (const float*)d_in[9];
    const float* p1_Ws  = (const float*)d_in[10];
    const float* p1_Wm  = (const float*)d_in[11];
    const float* p1_bm  = (const float*)d_in[12];
    const float* p1_g   = (const float*)d_in[13];
    const float* p1_bt  = (const float*)d_in[14];
    const float* lse2_W = (const float*)d_in[15];
    const float* lse2_b = (const float*)d_in[16];
    const float* lse2_g = (const float*)d_in[17];
    const float* lse2_bt = (const float*)d_in[18];
    const float* p2_Wc1 = (const float*)d_in[19];
    const float* p2_Wc2 = (const float*)d_in[20];
    const float* p2_Ws  = (const float*)d_in[21];
    const float* p2_Wm  = (const float*)d_in[22];
    const float* p2_bm  = (const float*)d_in[23];
    const float* p2_g   = (const float*)d_in[24];
    const float* p2_bt  = (const float*)d_in[25];
    const float* mlp2_W = (const float*)d_in[26];
    const float* mlp2_b = (const float*)d_in[27];
    const float* sc_W   = (const float*)d_in[28];
    const float* sc_b   = (const float*)d_in[29];
    const float* sc_g   = (const float*)d_in[30];
    const float* sc_bt  = (const float*)d_in[31];
    float* out = (float*)d_out;

    int prep_blocks = 11 + (BB*NCELL)/256 + (BB*NN*CIN + 255)/256;
    prep_all<<<prep_blocks, 256>>>(mlp1_W, lse1_W, lse2_W, p1_Wc1, p1_Wc2, p1_Wm,
                                   p2_Wc1, p2_Wc2, p2_Wm, mlp2_W, sc_W, sc_g, features);
    grid_count<<<(BB*NN + 255)/256, 256>>>(coords);
    grid_scan<<<BB, 1024>>>();
    grid_scatter<<<(BB*NN + 255)/256, 256>>>(coords);
    knn_grid<<<dim3(NN/8, BB), 256>>>();
    fused_kernel<<<(BB*NN)/8, 256>>>(coords, mlp1_b, lse1_b, lse1_g, lse1_bt,
                                     p1_Ws, p1_bm, p1_g, p1_bt,
                                     lse2_b, lse2_g, lse2_bt,
                                     p2_Ws, p2_bm, p2_g, p2_bt,
                                     mlp2_b, sc_b, sc_g, sc_bt, out);
}

// round 11
// speedup vs baseline: 1.0765x; 1.0765x over previous
#include <cuda_runtime.h>
#include <math.h>

#define BB 2
#define NN 8192
#define KNN 16
#define CIN 32
#define FULLW 0xffffffffu
#define KTILE 1024

// ---------------- scratch ----------------
__device__ float  g_feat_t[BB*NN*CIN];
__device__ float4 g_nb[BB*NN*KNN]; // (nx, ny, nz, dist) per point per k
// weights, repacked by prep
__device__ float g_mlp1Wt[32*32];
__device__ float g_lse1We[3*32];
__device__ float g_lse1Wn[4*32];
__device__ float g_lse2We[3*32];
__device__ float g_lse2Wn[4*32];
__device__ float g_p1c1p[512];
__device__ float g_p1c2p[512];
__device__ float g_p1wmt[64*32];
__device__ float g_p2c1p[512];
__device__ float g_p2c2p[512];
__device__ float g_p2wmt[64*64];
__device__ float g_mlp2t[64*128];
__device__ float g_scWt[32*128];   // pre-scaled by sc_g*bns

// ---------------- prep: weights + feat transpose ----------------
__global__ void prep_all(
    const float* __restrict__ mlp1_W,
    const float* __restrict__ lse1_W,
    const float* __restrict__ lse2_W,
    const float* __restrict__ p1c1, const float* __restrict__ p1c2, const float* __restrict__ p1wm,
    const float* __restrict__ p2c1, const float* __restrict__ p2c2, const float* __restrict__ p2wm,
    const float* __restrict__ mlp2_W, const float* __restrict__ sc_W,
    const float* __restrict__ sc_g, const float* __restrict__ features)
{
    const float bns = rsqrtf(1.0f + 1e-5f);
    int t = threadIdx.x;
    int bid = blockIdx.x;
    if (bid < 11) {
        switch (bid) {
            case 0:
                for (int i = t; i < 32*32; i += 256) g_mlp1Wt[(i%32)*32 + (i/32)] = mlp1_W[i];
                break;
            case 1:
                if (t < 32) {
                    for (int d = 0; d < 3; d++) {
                        g_lse1We[d*32+t] = lse1_W[t*10+d]   + lse1_W[t*10+6+d];
                        g_lse1Wn[d*32+t] = lse1_W[t*10+3+d] - lse1_W[t*10+6+d];
                    }
                    g_lse1Wn[3*32+t] = lse1_W[t*10+9];
                }
                break;
            case 2:
                if (t < 32) {
                    for (int d = 0; d < 3; d++) {
                        g_lse2We[d*32+t] = lse2_W[t*10+d]   + lse2_W[t*10+6+d];
                        g_lse2Wn[d*32+t] = lse2_W[t*10+3+d] - lse2_W[t*10+6+d];
                    }
                    g_lse2Wn[3*32+t] = lse2_W[t*10+9];
                }
                break;
            case 3:
                for (int i = t; i < 512; i += 256) {
                    int j = i / 64, c = i % 64;
                    g_p1c1p[((c>>2)*8 + j)*4 + (c&3)] = p1c1[i];
                }
                break;
            case 4:
                for (int i = t; i < 512; i += 256) {
                    int r = i / 8, c = i % 8;
                    g_p1c2p[((c>>2)*64 + r)*4 + (c&3)] = p1c2[i];
                }
                break;
            case 5:
                for (int i = t; i < 32*64; i += 256) g_p1wmt[(i%64)*32 + (i/64)] = p1wm[i];
                break;
            case 6:
                for (int i = t; i < 512; i += 256) {
                    int j = i / 64, c = i % 64;
                    g_p2c1p[((c>>2)*8 + j)*4 + (c&3)] = p2c1[i];
                }
                break;
            case 7:
                for (int i = t; i < 512; i += 256) {
                    int r = i / 8, c = i % 8;
                    g_p2c2p[((c>>2)*64 + r)*4 + (c&3)] = p2c2[i];
                }
                break;
            case 8:
                for (int i = t; i < 64*64; i += 256) g_p2wmt[(i%64)*64 + (i/64)] = p2wm[i];
                break;
            case 9:
                for (int i = t; i < 128*64; i += 256) g_mlp2t[(i%64)*128 + (i/64)] = mlp2_W[i];
                break;
            default:
                for (int i = t; i < 128*32; i += 256) {
                    int oc = i / 32, d = i % 32;
                    g_scWt[d*128 + oc] = sc_W[i] * sc_g[oc] * bns;
                }
                break;
        }
        return;
    }
    bid -= 11;
    {   // feat transpose
        int gid = bid*256 + t;
        if (gid < BB*NN*CIN) {
            int c = gid & 31;
            int p = gid >> 5;
            int b = p / NN, n = p % NN;
            g_feat_t[gid] = features[((size_t)b*CIN + c)*NN + n];
        }
    }
}

// ---------------- KNN brute v2: 4 queries/warp, buffered + bitonic flush ----------------
__device__ __forceinline__ void bitonic32(float& key, int& pay, int lane) {
#pragma unroll
    for (int k = 2; k <= 32; k <<= 1) {
#pragma unroll
        for (int j = k >> 1; j > 0; j >>= 1) {
            float ok = __shfl_xor_sync(FULLW, key, j);
            int   op = __shfl_xor_sync(FULLW, pay, j);
            bool takeMin = (((lane & j) == 0) == ((lane & k) == 0));
            bool less = (ok < key) || (ok == key && op < pay);
            if (takeMin ? less : !less) { key = ok; pay = op; }
        }
    }
}

// merge sorted top-16 (lanes 0..15 of lv/li, ascending) with sorted-asc 32-chunk
__device__ __forceinline__ void merge_chunk(
    float key, int pay, float& lv, int& li, float& tau, int lane)
{
    float ck = __shfl_xor_sync(FULLW, key, 31);
    int   cp = __shfl_xor_sync(FULLW, pay, 31);
    float v  = (lane < 16) ? lv : ck;
    int   vp = (lane < 16) ? li : cp;
#pragma unroll
    for (int j = 16; j > 0; j >>= 1) {
        float ov  = __shfl_xor_sync(FULLW, v, j);
        int   ovp = __shfl_xor_sync(FULLW, vp, j);
        bool takeMin = ((lane & j) == 0);
        bool less = (ov < v) || (ov == v && ovp < vp);
        if (takeMin ? less : !less) { v = ov; vp = ovp; }
    }
    lv = v; li = vp;
    tau = __shfl_sync(FULLW, v, 15);
}

__device__ __forceinline__ void flush_full(
    volatile float* bD, volatile int* bA, int base,
    float& lv, int& li, float& tau, int lane)
{
    __syncwarp();
    float key = bD[base + lane];
    int   pay = bA[base + lane];
    bitonic32(key, pay, lane);
    merge_chunk(key, pay, lv, li, tau, lane);
}

__device__ __forceinline__ void flush_partial(
    volatile float* bD, volatile int* bA, int nbuf,
    float& lv, int& li, float& tau, int lane)
{
    if (nbuf > 0) {
        __syncwarp();
        float key = (lane < nbuf) ? bD[lane] : 3.4e38f;
        int   pay = (lane < nbuf) ? bA[lane] : 0x7fffffff;
        bitonic32(key, pay, lane);
        merge_chunk(key, pay, lv, li, tau, lane);
    }
}

__global__ void __launch_bounds__(256) knn_brute(const float* __restrict__ coords) {
    __shared__ float4 tile[KTILE];
    __shared__ float  sD[8][4][64];
    __shared__ int    sA[8][4][64];

    int b = blockIdx.y;
    int warp = threadIdx.x >> 5, lane = threadIdx.x & 31;
    int qb = (blockIdx.x * 8 + warp) * 4;
    const float* cb = coords + (size_t)b*NN*3;

    float qx[4], qy[4], qz[4];
#pragma unroll
    for (int q = 0; q < 4; q++) {
        qx[q] = cb[(qb+q)*3+0]; qy[q] = cb[(qb+q)*3+1]; qz[q] = cb[(qb+q)*3+2];
    }

    float lv[4]; int li[4]; float tau[4]; int nbuf[4];
#pragma unroll
    for (int q = 0; q < 4; q++) { lv[q] = 3.4e38f; li[q] = 0x7fffffff; tau[q] = 3.4e38f; nbuf[q] = 0; }
    bool seeded = false;

    for (int t0 = 0; t0 < NN; t0 += KTILE) {
        __syncthreads();
        for (int u = threadIdx.x; u < KTILE; u += 256) {
            int j = t0 + u;
            float x = cb[j*3+0], y = cb[j*3+1], z = cb[j*3+2];
            tile[u] = make_float4(-2.0f*x, -2.0f*y, -2.0f*z, x*x + y*y + z*z);
        }
        __syncthreads();

        for (int u = 0; u < KTILE; u += 32) {
            float4 c = tile[u + lane];
            int jc = t0 + u + lane;
            float d2[4];
#pragma unroll
            for (int q = 0; q < 4; q++)
                d2[q] = fmaf(qx[q], c.x, fmaf(qy[q], c.y, fmaf(qz[q], c.z, c.w)));

            if (!seeded) {
#pragma unroll
                for (int q = 0; q < 4; q++) {
                    float key = d2[q]; int pay = jc;
                    bitonic32(key, pay, lane);
                    lv[q] = (lane < 16) ? key : 3.4e38f;
                    li[q] = pay;
                    tau[q] = __shfl_sync(FULLW, key, 15);
                }
                seeded = true;
                continue;
            }

            bool anyq = (d2[0] < tau[0]) | (d2[1] < tau[1]) | (d2[2] < tau[2]) | (d2[3] < tau[3]);
            if (__ballot_sync(FULLW, anyq)) {
#pragma unroll
                for (int q = 0; q < 4; q++) {
                    unsigned m = __ballot_sync(FULLW, d2[q] < tau[q]);
                    if (m) {
                        int rank = __popc(m & ((1u << lane) - 1u));
                        if (d2[q] < tau[q]) {
                            sD[warp][q][nbuf[q] + rank] = d2[q];
                            sA[warp][q][nbuf[q] + rank] = jc;
                        }
                        nbuf[q] += __popc(m);
                        while (nbuf[q] >= 32) {
                            nbuf[q] -= 32;
                            flush_full(&sD[warp][q][0], &sA[warp][q][0], nbuf[q],
                                       lv[q], li[q], tau[q], lane);
                        }
                    }
                }
            }
        }
    }

#pragma unroll
    for (int q = 0; q < 4; q++)
        flush_partial(&sD[warp][q][0], &sA[warp][q][0], nbuf[q], lv[q], li[q], tau[q], lane);

    // write neighbor tuples (sorted ascending by (d2, idx) = top_k order)
#pragma unroll
    for (int q = 0; q < 4; q++) {
        if (lane < KNN) {
            int j = li[q];
            float nx = cb[j*3+0], ny = cb[j*3+1], nz = cb[j*3+2];
            float dx = qx[q]-nx, dy = qy[q]-ny, dz = qz[q]-nz;
            g_nb[((size_t)b*NN + qb+q)*KNN + lane] =
                make_float4(nx, ny, nz, sqrtf(fmaf(dx, dx, fmaf(dy, dy, dz*dz))));
        }
    }
}

// ---------------- fused per-point pipeline (8 points per 256-thread block) ----------------
__device__ __forceinline__ float sigmoidf_(float x) { return 1.0f / (1.0f + expf(-x)); }

struct SArena {
    float4 nb[8][16];
    float  A[8][64];
    float  M[8][64];
    float  Hs[8][8];
    float  Sp[8][16];
    float  Fe8[32*8];
    float  F8[64*8];
    float  Out8[64*8];
    float  Part[4096];
};

template<int NOUT>
__device__ __forceinline__ void stage(
    SArena* s, float featv, float cx, float cy, float cz,
    const float* __restrict__ We, const float* __restrict__ Wn,
    const float* __restrict__ bl, const float* __restrict__ gl, const float* __restrict__ btl,
    const float* __restrict__ c1p, const float* __restrict__ c2p,
    const float* __restrict__ Ws,
    const float* __restrict__ Wmt, const float* __restrict__ bm,
    const float* __restrict__ gm,  const float* __restrict__ btm,
    int lane, int warp, int tid)
{
    const float bns = rsqrtf(1.0f + 1e-5f);
    float we0 = We[0*32+lane], we1 = We[1*32+lane], we2 = We[2*32+lane];
    float wn0 = Wn[0*32+lane], wn1 = Wn[1*32+lane], wn2 = Wn[2*32+lane], wn3 = Wn[3*32+lane];
    float scl = gl[lane]*bns, shb = btl[lane];
    float base = bl[lane];
    base = fmaf(we0, cx, fmaf(we1, cy, fmaf(we2, cz, base)));

    float e[16];
    float avg = 0.f, mx = -3.4e38f;
#pragma unroll
    for (int k = 0; k < 16; k++) {
        float4 nb = s->nb[warp][k];
        float v = fmaf(wn0, nb.x, fmaf(wn1, nb.y, fmaf(wn2, nb.z, fmaf(wn3, nb.w, base))));
        v = fmaxf(scl*v + shb, 0.f);
        e[k] = v;
        avg += v;
        mx = fmaxf(mx, v);
    }
    avg *= 0.0625f;
    s->A[warp][lane] = avg; s->A[warp][32 + lane] = featv;
    s->M[warp][lane] = mx;  s->M[warp][32 + lane] = featv;
    __syncwarp();

    {
        int j = lane & 7;
        int srcbit = (lane >> 3) & 1;
        int chalf = lane >> 4;
        const float* S = srcbit ? s->M[warp] : s->A[warp];
        float h = 0.f;
#pragma unroll
        for (int cq = 0; cq < 8; cq++) {
            int quad = chalf*8 + cq;
            float4 w4 = *reinterpret_cast<const float4*>(&c1p[(quad*8 + j)*4]);
            float4 a4 = *reinterpret_cast<const float4*>(&S[chalf*32 + cq*4]);
            h = fmaf(w4.x, a4.x, fmaf(w4.y, a4.y, fmaf(w4.z, a4.z, fmaf(w4.w, a4.w, h))));
        }
        h += __shfl_xor_sync(FULLW, h, 16);
        float h2 = fmaxf(h, 0.f);
        float hsv = h2 + __shfl_xor_sync(FULLW, h2, 8);
        if (lane < 8) s->Hs[warp][lane] = hsv;
    }
    __syncwarp();

    float4 hs0 = *reinterpret_cast<const float4*>(&s->Hs[warp][0]);
    float4 hs1 = *reinterpret_cast<const float4*>(&s->Hs[warp][4]);
    float a, b2;
    {
        float4 w0 = *reinterpret_cast<const float4*>(&c2p[lane*4]);
        float4 w1 = *reinterpret_cast<const float4*>(&c2p[(64 + lane)*4]);
        a = w0.x*hs0.x + w0.y*hs0.y + w0.z*hs0.z + w0.w*hs0.w
          + w1.x*hs1.x + w1.y*hs1.y + w1.z*hs1.z + w1.w*hs1.w;
        float4 v0 = *reinterpret_cast<const float4*>(&c2p[(32 + lane)*4]);
        float4 v1 = *reinterpret_cast<const float4*>(&c2p[(96 + lane)*4]);
        b2 = v0.x*hs0.x + v0.y*hs0.y + v0.z*hs0.z + v0.w*hs0.w
           + v1.x*hs1.x + v1.y*hs1.y + v1.z*hs1.z + v1.w*hs1.w;
    }
    float chA = sigmoidf_(a), chB = sigmoidf_(b2);
    float xf = featv * chB;

    float vs[16], vm[16];
#pragma unroll
    for (int k = 0; k < 16; k++) {
        float ek = e[k] * chA;
        e[k] = ek;
        vs[k] = ek + xf;
        vm[k] = fmaxf(ek, xf);
    }
    {
        bool up = (lane & 16);
#pragma unroll
        for (int i = 0; i < 8; i++) {
            float ss = up ? vs[i] : vs[i+8];
            float ks = up ? vs[i+8] : vs[i];
            vs[i] = ks + __shfl_xor_sync(FULLW, ss, 16);
            float sm2 = up ? vm[i] : vm[i+8];
            float km = up ? vm[i+8] : vm[i];
            vm[i] = fmaxf(km, __shfl_xor_sync(FULLW, sm2, 16));
        }
    }
    {
        bool up = (lane & 8);
#pragma unroll
        for (int i = 0; i < 4; i++) {
            float ss = up ? vs[i] : vs[i+4];
            float ks = up ? vs[i+4] : vs[i];
            vs[i] = ks + __shfl_xor_sync(FULLW, ss, 8);
            float sm2 = up ? vm[i] : vm[i+4];
            float km = up ? vm[i+4] : vm[i];
            vm[i] = fmaxf(km, __shfl_xor_sync(FULLW, sm2, 8));
        }
    }
    {
        bool up = (lane & 4);
#pragma unroll
        for (int i = 0; i < 2; i++) {
            float ss = up ? vs[i] : vs[i+2];
            float ks = up ? vs[i+2] : vs[i];
            vs[i] = ks + __shfl_xor_sync(FULLW, ss, 4);
            float sm2 = up ? vm[i] : vm[i+2];
            float km = up ? vm[i+2] : vm[i];
            vm[i] = fmaxf(km, __shfl_xor_sync(FULLW, sm2, 4));
        }
    }
    {
        bool up = (lane & 2);
        float ss = up ? vs[0] : vs[1];
        float ks = up ? vs[1] : vs[0];
        vs[0] = ks + __shfl_xor_sync(FULLW, ss, 2);
        float sm2 = up ? vm[0] : vm[1];
        float km = up ? vm[1] : vm[0];
        vm[0] = fmaxf(km, __shfl_xor_sync(FULLW, sm2, 2));
    }
    vs[0] += __shfl_xor_sync(FULLW, vs[0], 1);
    vm[0] = fmaxf(vm[0], __shfl_xor_sync(FULLW, vm[0], 1));

    float ws0 = Ws[0], ws1 = Ws[1];
    float sp = sigmoidf_(ws0 * vs[0] * (1.0f/64.0f) + ws1 * vm[0]);
    int kL = (((lane>>4)&1)<<3) | (((lane>>3)&1)<<2) | (((lane>>2)&1)<<1) | ((lane>>1)&1);
    if (!(lane & 1)) s->Sp[warp][kL] = sp;
    float sps = sp;
#pragma unroll
    for (int off = 16; off > 0; off >>= 1) sps += __shfl_xor_sync(FULLW, sps, off);
    sps *= 0.5f;
    __syncwarp();

    float fA = 0.f;
#pragma unroll
    for (int k = 0; k < 16; k++) fA = fmaf(e[k], s->Sp[warp][k], fA);

    s->F8[lane*8 + warp]        = fA;
    s->F8[(32 + lane)*8 + warp] = xf * sps;
    __syncthreads();

    constexpr int G = NOUT/32;
    {
        float acc[G][8];
#pragma unroll
        for (int g = 0; g < G; g++)
#pragma unroll
            for (int p = 0; p < 8; p++) acc[g][p] = 0.f;
        int jb = warp * 8;
#pragma unroll
        for (int jj = 0; jj < 8; jj++) {
            int j = jb + jj;
            float4 a0 = *reinterpret_cast<const float4*>(&s->F8[j*8]);
            float4 a1 = *reinterpret_cast<const float4*>(&s->F8[j*8+4]);
#pragma unroll
            for (int g = 0; g < G; g++) {
                float wv = Wmt[j*NOUT + g*32 + lane];
                acc[g][0] = fmaf(wv, a0.x, acc[g][0]);
                acc[g][1] = fmaf(wv, a0.y, acc[g][1]);
                acc[g][2] = fmaf(wv, a0.z, acc[g][2]);
                acc[g][3] = fmaf(wv, a0.w, acc[g][3]);
                acc[g][4] = fmaf(wv, a1.x, acc[g][4]);
                acc[g][5] = fmaf(wv, a1.y, acc[g][5]);
                acc[g][6] = fmaf(wv, a1.z, acc[g][6]);
                acc[g][7] = fmaf(wv, a1.w, acc[g][7]);
            }
        }
#pragma unroll
        for (int g = 0; g < G; g++) {
            int bidx = (warp*NOUT + g*32 + lane)*8;
            *reinterpret_cast<float4*>(&s->Part[bidx])   = make_float4(acc[g][0], acc[g][1], acc[g][2], acc[g][3]);
            *reinterpret_cast<float4*>(&s->Part[bidx+4]) = make_float4(acc[g][4], acc[g][5], acc[g][6], acc[g][7]);
        }
    }
    __syncthreads();

#pragma unroll
    for (int g = 0; g < G; g++) {
        int idx = g*256 + tid;
        int oc = idx >> 3, pp = idx & 7;
        float sum = 0.f;
#pragma unroll
        for (int w = 0; w < 8; w++) sum += s->Part[(w*NOUT + oc)*8 + pp];
        sum += bm[oc];
        s->Out8[idx] = fmaxf(gm[oc]*bns*sum + btm[oc], 0.f);
    }
    __syncthreads();
}

__global__ void __launch_bounds__(256) fused_kernel(
    const float* __restrict__ coords,
    const float* __restrict__ mlp1_b,
    const float* __restrict__ lse1_b, const float* __restrict__ lse1_g, const float* __restrict__ lse1_bt,
    const float* __restrict__ p1_Ws,  const float* __restrict__ p1_bm,  const float* __restrict__ p1_g, const float* __restrict__ p1_bt,
    const float* __restrict__ lse2_b, const float* __restrict__ lse2_g, const float* __restrict__ lse2_bt,
    const float* __restrict__ p2_Ws,  const float* __restrict__ p2_bm,  const float* __restrict__ p2_g, const float* __restrict__ p2_bt,
    const float* __restrict__ mlp2_b,
    const float* __restrict__ sc_b, const float* __restrict__ sc_g, const float* __restrict__ sc_bt,
    float* __restrict__ out)
{
    __shared__ SArena s;

    int tid = threadIdx.x;
    int warp = tid >> 5, lane = tid & 31;
    int p = blockIdx.x * 8 + warp;
    int b = p >> 13, n = p & (NN - 1);

    s.Fe8[lane*8 + warp] = g_feat_t[p*CIN + lane];

    const float* cb = coords + ((size_t)b*NN + n)*3;
    float cx = cb[0], cy = cb[1], cz = cb[2];
    if (lane < 16) {
        s.nb[warp][lane] = g_nb[(size_t)p*KNN + lane];
    }
    __syncwarp();

    float x1;
    {
        float acc = mlp1_b[lane];
#pragma unroll
        for (int d = 0; d < 32; d++) acc = fmaf(g_mlp1Wt[d*32 + lane], s.Fe8[d*8 + warp], acc);
        x1 = acc >= 0.f ? acc : 0.2f*acc;
    }

    stage<32>(&s, x1, cx, cy, cz, g_lse1We, g_lse1Wn, lse1_b, lse1_g, lse1_bt,
              g_p1c1p, g_p1c2p, p1_Ws, g_p1wmt, p1_bm, p1_g, p1_bt, lane, warp, tid);
    float o1 = s.Out8[lane*8 + warp];

    stage<64>(&s, o1, cx, cy, cz, g_lse2We, g_lse2Wn, lse2_b, lse2_g, lse2_bt,
              g_p2c1p, g_p2c2p, p2_Ws, g_p2wmt, p2_bm, p2_g, p2_bt, lane, warp, tid);

    {
        int slice = tid >> 6;
        int oc0 = (tid & 63) * 2;
        float acc0[8], acc1[8];
#pragma unroll
        for (int q = 0; q < 8; q++) { acc0[q] = 0.f; acc1[q] = 0.f; }
#pragma unroll
        for (int jj = 0; jj < 16; jj++) {
            int j = slice*16 + jj;
            float2 w2 = *reinterpret_cast<const float2*>(&g_mlp2t[j*128 + oc0]);
            float4 a0 = *reinterpret_cast<const float4*>(&s.Out8[j*8]);
            float4 a1 = *reinterpret_cast<const float4*>(&s.Out8[j*8+4]);
            acc0[0] = fmaf(w2.x, a0.x, acc0[0]); acc1[0] = fmaf(w2.y, a0.x, acc1[0]);
            acc0[1] = fmaf(w2.x, a0.y, acc0[1]); acc1[1] = fmaf(w2.y, a0.y, acc1[1]);
            acc0[2] = fmaf(w2.x, a0.z, acc0[2]); acc1[2] = fmaf(w2.y, a0.z, acc1[2]);
            acc0[3] = fmaf(w2.x, a0.w, acc0[3]); acc1[3] = fmaf(w2.y, a0.w, acc1[3]);
            acc0[4] = fmaf(w2.x, a1.x, acc0[4]); acc1[4] = fmaf(w2.y, a1.x, acc1[4]);
            acc0[5] = fmaf(w2.x, a1.y, acc0[5]); acc1[5] = fmaf(w2.y, a1.y, acc1[5]);
            acc0[6] = fmaf(w2.x, a1.z, acc0[6]); acc1[6] = fmaf(w2.y, a1.z, acc1[6]);
            acc0[7] = fmaf(w2.x, a1.w, acc0[7]); acc1[7] = fmaf(w2.y, a1.w, acc1[7]);
        }
#pragma unroll
        for (int dd = 0; dd < 8; dd++) {
            int d = slice*8 + dd;
            float2 w2 = *reinterpret_cast<const float2*>(&g_scWt[d*128 + oc0]);
            float4 f0 = *reinterpret_cast<const float4*>(&s.Fe8[d*8]);
            float4 f1 = *reinterpret_cast<const float4*>(&s.Fe8[d*8+4]);
            acc0[0] = fmaf(w2.x, f0.x, acc0[0]); acc1[0] = fmaf(w2.y, f0.x, acc1[0]);
            acc0[1] = fmaf(w2.x, f0.y, acc0[1]); acc1[1] = fmaf(w2.y, f0.y, acc1[1]);
            acc0[2] = fmaf(w2.x, f0.z, acc0[2]); acc1[2] = fmaf(w2.y, f0.z, acc1[2]);
            acc0[3] = fmaf(w2.x, f0.w, acc0[3]); acc1[3] = fmaf(w2.y, f0.w, acc1[3]);
            acc0[4] = fmaf(w2.x, f1.x, acc0[4]); acc1[4] = fmaf(w2.y, f1.x, acc1[4]);
            acc0[5] = fmaf(w2.x, f1.y, acc0[5]); acc1[5] = fmaf(w2.y, f1.y, acc1[5]);
            acc0[6] = fmaf(w2.x, f1.z, acc0[6]); acc1[6] = fmaf(w2.y, f1.z, acc1[6]);
            acc0[7] = fmaf(w2.x, f1.w, acc0[7]); acc1[7] = fmaf(w2.y, f1.w, acc1[7]);
        }
        int b0 = (slice*128 + oc0)*8;
        *reinterpret_cast<float4*>(&s.Part[b0])     = make_float4(acc0[0], acc0[1], acc0[2], acc0[3]);
        *reinterpret_cast<float4*>(&s.Part[b0+4])   = make_float4(acc0[4], acc0[5], acc0[6], acc0[7]);
        *reinterpret_cast<float4*>(&s.Part[b0+8])   = make_float4(acc1[0], acc1[1], acc1[2], acc1[3]);
        *reinterpret_cast<float4*>(&s.Part[b0+12])  = make_float4(acc1[4], acc1[5], acc1[6], acc1[7]);
    }
    __syncthreads();

    {
        const float bns = rsqrtf(1.0f + 1e-5f);
        int oc = tid & 127;
        int ph = tid >> 7;
        float4 v = make_float4(0.f, 0.f, 0.f, 0.f);
#pragma unroll
        for (int sl = 0; sl < 4; sl++) {
            float4 t = *reinterpret_cast<const float4*>(&s.Part[(sl*128 + oc)*8 + ph*4]);
            v.x += t.x; v.y += t.y; v.z += t.z; v.w += t.w;
        }
        float basev = mlp2_b[oc] + sc_g[oc]*bns*sc_b[oc] + sc_bt[oc];
        v.x += basev; v.y += basev; v.z += basev; v.w += basev;
        v.x = v.x >= 0.f ? v.x : 0.01f*v.x;
        v.y = v.y >= 0.f ? v.y : 0.01f*v.y;
        v.z = v.z >= 0.f ? v.z : 0.01f*v.z;
        v.w = v.w >= 0.f ? v.w : 0.01f*v.w;

        int p0 = blockIdx.x * 8;
        int b0 = p0 >> 13, n0 = p0 & (NN - 1);
        *reinterpret_cast<float4*>(&out[((size_t)(b0*128 + oc))*NN + n0 + ph*4]) = v;
    }
}

// ---------------- launch ----------------
extern "C" void kernel_launch(void* const* d_in, const int* in_sizes, int n_in,
                              void* d_out, int out_size) {
    const float* coords   = (const float*)d_in[0];
    const float* features = (const float*)d_in[1];
    const float* mlp1_W = (const float*)d_in[2];
    const float* mlp1_b = (const float*)d_in[3];
    const float* lse1_W = (const float*)d_in[4];
    const float* lse1_b = (const float*)d_in[5];
    const float* lse1_g = (const float*)d_in[6];
    const float* lse1_bt = (const float*)d_in[7];
    const float* p1_Wc1 = (const float*)d_in[8];
    const float* p1_Wc2 = (const float*)d_in[9];
    const float* p1_Ws  = (const float*)d_in[10];
    const float* p1_Wm  = (const float*)d_in[11];
    const float* p1_bm  = (const float*)d_in[12];
    const float* p1_g   = (const float*)d_in[13];
    const float* p1_bt  = (const float*)d_in[14];
    const float* lse2_W = (const float*)d_in[15];
    const float* lse2_b = (const float*)d_in[16];
    const float* lse2_g = (const float*)d_in[17];
    const float* lse2_bt = (const float*)d_in[18];
    const float* p2_Wc1 = (const float*)d_in[19];
    const float* p2_Wc2 = (const float*)d_in[20];
    const float* p2_Ws  = (const float*)d_in[21];
    const float* p2_Wm  = (const float*)d_in[22];
    const float* p2_bm  = (const float*)d_in[23];
    const float* p2_g   = (const float*)d_in[24];
    const float* p2_bt  = (const float*)d_in[25];
    const float* mlp2_W = (const float*)d_in[26];
    const float* mlp2_b = (const float*)d_in[27];
    const float* sc_W   = (const float*)d_in[28];
    const float* sc_b   = (const float*)d_in[29];
    const float* sc_g   = (const float*)d_in[30];
    const float* sc_bt  = (const float*)d_in[31];
    float* out = (float*)d_out;

    int prep_blocks = 11 + (BB*NN*CIN + 255)/256;
    prep_all<<<prep_blocks, 256>>>(mlp1_W, lse1_W, lse2_W, p1_Wc1, p1_Wc2, p1_Wm,
                                   p2_Wc1, p2_Wc2, p2_Wm, mlp2_W, sc_W, sc_g, features);
    knn_brute<<<dim3(NN/32, BB), 256>>>(coords);
    fused_kernel<<<(BB*NN)/8, 256>>>(coords, mlp1_b, lse1_b, lse1_g, lse1_bt,
                                     p1_Ws, p1_bm, p1_g, p1_bt,
                                     lse2_b, lse2_g, lse2_bt,
                                     p2_Ws, p2_bm, p2_g, p2_bt,
                                     mlp2_b, sc_b, sc_g, sc_bt, out);
}